// round 4
// baseline (speedup 1.0000x reference)
#include <cuda_runtime.h>
#include <cstdint>
#include <cstddef>

#define BATCHN 10
#define HID    128
#define OUTD   7
#define TLEN   2048
#define NCTA   8
#define KPC    16      // HID / NCTA hidden units owned per CTA
#define TPB    640     // 20 warps; 64 threads (2 warps) per batch

typedef unsigned long long ull;

__device__ __forceinline__ uint32_t sm2u(const void* p) {
    return (uint32_t)__cvta_generic_to_shared(const_cast<void*>(p));
}
__device__ __forceinline__ uint32_t ctarank() {
    uint32_t r; asm("mov.u32 %0, %%cluster_ctarank;" : "=r"(r)); return r;
}
__device__ __forceinline__ void dst_f32(uint32_t saddr, uint32_t rk, float v) {
    uint32_t ra;
    asm volatile("mapa.shared::cluster.u32 %0, %1, %2;" : "=r"(ra) : "r"(saddr), "r"(rk));
    asm volatile("st.shared::cluster.f32 [%0], %1;" :: "r"(ra), "f"(v) : "memory");
}
__device__ __forceinline__ void dst_u64(uint32_t saddr, uint32_t rk, ull v) {
    uint32_t ra;
    asm volatile("mapa.shared::cluster.u32 %0, %1, %2;" : "=r"(ra) : "r"(saddr), "r"(rk));
    asm volatile("st.shared::cluster.b64 [%0], %1;" :: "r"(ra), "l"(v) : "memory");
}
__device__ __forceinline__ ull fma2(ull a, ull b, ull c) {
    ull d; asm("fma.rn.f32x2 %0, %1, %2, %3;" : "=l"(d) : "l"(a), "l"(b), "l"(c)); return d;
}
__device__ __forceinline__ ull pk2(float lo, float hi) {
    ull r; asm("mov.b64 %0, {%1, %2};" : "=l"(r) : "f"(lo), "f"(hi)); return r;
}
__device__ __forceinline__ float2 unpk2(ull v) {
    float2 f; asm("mov.b64 {%0, %1}, %2;" : "=f"(f.x), "=f"(f.y) : "l"(v)); return f;
}
__device__ __forceinline__ float fsig(float x)  { return __fdividef(1.f, 1.f + __expf(-x)); }
__device__ __forceinline__ float ftanh(float x) { return 2.f * __fdividef(1.f, 1.f + __expf(-2.f * x)) - 1.f; }

#define FULLM 0xffffffffu

__global__ void __cluster_dims__(NCTA, 1, 1) __launch_bounds__(TPB, 1)
lstm_decoder_kernel(const float* __restrict__ h0,
                    const float* __restrict__ c0,
                    const float* __restrict__ tonehot,   // (TLEN+1, 1, OUTD)
                    const void*  __restrict__ tfraw,     // tf_mask (dtype autodetect)
                    const float* __restrict__ W_ih,      // (4*HID, OUTD)
                    const float* __restrict__ W_hh,      // (4*HID, HID)
                    const float* __restrict__ b_ih,
                    const float* __restrict__ b_hh,
                    const float* __restrict__ W_out,     // (OUT, HID)
                    const float* __restrict__ b_out,
                    float* __restrict__ out)             // [143360 lp | 1280 hT | 1280 cT]
{
    __shared__ __align__(16) float h_s[2][BATCHN][HID];    // double-buffered hidden state
    __shared__ float gates_s[BATCHN * 64];                 // activated gates (CTA k-slice)
    __shared__ float plog_s[2][NCTA][BATCHN * OUTD];       // partial logits per CTA
    __shared__ float wih_s[4 * HID * OUTD];
    __shared__ int   tgt_s[TLEN];
    __shared__ unsigned char tf_s[TLEN];
    __shared__ float bout_s[OUTD];
    __shared__ int   tfmode_s;

    const int tid   = threadIdx.x;
    const int lane  = tid & 31;
    const int b     = tid >> 6;          // batch 0..9 (2 warps per batch)
    const int r     = tid & 63;          // gate row within CTA slice
    const int type  = r >> 4;            // 0=i 1=f 2=g 3=o
    const int kl    = r & 15;
    const bool evenw = (tid & 32) == 0;  // first warp of the batch group
    const uint32_t rank = ctarank();

    const int g = type * HID + (int)rank * KPC + kl;

    // W_hh row g for ONE batch: 32 packed f32x2 (64 regs)
    ull wp[HID / 2];
#pragma unroll
    for (int i = 0; i < HID / 4; i++) {
        float4 v = reinterpret_cast<const float4*>(W_hh + (size_t)g * HID)[i];
        wp[2*i]   = pk2(v.x, v.y);
        wp[2*i+1] = pk2(v.z, v.w);
    }
    const float biasg = b_ih[g] + b_hh[g];
    const int   gbase = g * OUTD;

    // pointwise role: r < 16 (lanes 0..15 of even warp) own (batch b, k=kl)
    const bool is_pw = r < KPC;
    const int  kg = (int)rank * KPC + kl;
    float cval = 0.f;
    float wout[OUTD];
    if (is_pw) {
        cval = c0[b * HID + kg];
#pragma unroll
        for (int o = 0; o < OUTD; o++) wout[o] = W_out[o * HID + kg];
    }

    // ---- init ----
    for (int i = tid; i < BATCHN * HID; i += TPB) ((float*)h_s[0])[i] = h0[i];
    for (int i = tid; i < 4 * HID * OUTD; i += TPB) wih_s[i] = W_ih[i];
    if (tid < OUTD) bout_s[tid] = b_out[tid];
    if (tid == 0) {                                   // tf dtype autodetect
        const int* ip = (const int*)tfraw;
        int mode = 0;
        for (int i = 0; i < 512; i++) {
            int v = ip[i];
            if (v == 0x3f800000) { mode = 1; break; }
            if (v != 0 && v != 1) mode = 2;
        }
        tfmode_s = mode;
    }
    __syncthreads();
    {
        const int mode = tfmode_s;
        for (int s = tid; s < TLEN; s += TPB) {
            unsigned char tv;
            if (mode == 0)      tv = ((const int*)tfraw)[s] != 0;
            else if (mode == 1) tv = ((const float*)tfraw)[s] != 0.f;
            else                tv = ((const unsigned char*)tfraw)[s] != 0;
            tf_s[s] = tv;
            const float* row = tonehot + (size_t)(s + 1) * OUTD;   // exactly one-hot
            int idx = 0; float best = row[0];
#pragma unroll
            for (int o = 1; o < OUTD; o++) { if (row[o] > best) { best = row[o]; idx = o; } }
            tgt_s[s] = idx;
        }
    }
    __syncthreads();
    asm volatile("barrier.cluster.arrive.aligned;" ::: "memory");
    asm volatile("barrier.cluster.wait.aligned;"   ::: "memory");

    // precomputed smem byte-offsets (uniform-ish)
    const uint32_t gsts = sm2u(&gates_s[b * 64 + r]);

    // ================= main sequential loop =================
    for (int t = 0; t < TLEN; t++) {
        const int p = t & 1;

        // ---- argmax of logits(t-1) for this warp's batch (redundant per warp; no publish) ----
        int xb = OUTD - 1;
        float slog = -1e30f, vmax = -1e30f;
        if (t > 0) {
            const int o = lane & 7;
            float s = -1e30f;
            if (lane < 8 && o < OUTD) {
                float pr[NCTA];
#pragma unroll
                for (int rr = 0; rr < NCTA; rr++) pr[rr] = plog_s[p][rr][b * OUTD + o];
                s = bout_s[o];
#pragma unroll
                for (int rr = 0; rr < NCTA; rr++) s += pr[rr];
            }
            float v = s;
            int   idx = (lane < 8 && o < OUTD) ? o : OUTD;
#pragma unroll
            for (int d = 4; d >= 1; d >>= 1) {
                float v2 = __shfl_xor_sync(FULLM, v, d, 8);
                int   i2 = __shfl_xor_sync(FULLM, idx, d, 8);
                if (v2 > v || (v2 == v && i2 < idx)) { v = v2; idx = i2; }
            }
            slog = s; vmax = v;
            const int ia = __shfl_sync(FULLM, idx, 0);
            xb = tf_s[t - 1] ? tgt_s[t - 1] : ia;
        }

        // ---- recurrent dot for one batch: 64 f32x2 FMAs, 32 LDS.128 ----
        ull acc0 = 0ull, acc1 = 0ull;
        const ulonglong2* hb = reinterpret_cast<const ulonglong2*>(h_s[p][b]);
#pragma unroll
        for (int i = 0; i < HID / 4; i++) {
            ulonglong2 u = hb[i];
            acc0 = fma2(u.x, wp[2*i],   acc0);
            acc1 = fma2(u.y, wp[2*i+1], acc1);
        }
        float2 f0 = unpk2(acc0), f1 = unpk2(acc1);
        float vb = (f0.x + f0.y) + (f1.x + f1.y) + biasg + wih_s[gbase + xb];
        vb = (type == 2) ? ftanh(vb) : fsig(vb);
        asm volatile("st.shared.f32 [%0], %1;" :: "r"(gsts), "f"(vb) : "memory");

        // ---- batch-group exchange (64 threads, named barrier per batch) ----
        asm volatile("bar.sync %0, 64;" :: "r"(1 + b) : "memory");

        // ---- pointwise for batch b on the 16 pw threads ----
        if (is_pw) {
            const int gb = b * 64 + kl;
            const float ig = gates_s[gb];
            const float fg = gates_s[gb + 16];
            const float gg = gates_s[gb + 32];
            const float og = gates_s[gb + 48];
            cval = fg * cval + ig * gg;
            const float h2 = og * ftanh(cval);

            // packed 8B broadcast (even pw lanes carry the pair)
            const float h2hi = __shfl_xor_sync(0x0000ffffu, h2, 1, 16);
            if ((kl & 1) == 0) {
                const ull hv = pk2(h2, h2hi);
                const uint32_t hoff = sm2u(&h_s[p ^ 1][b][kg]);
#pragma unroll
                for (uint32_t rr = 0; rr < NCTA; rr++) dst_u64(hoff, rr, hv);
            }

            // partial logits for this CTA's slice (reduce 16 lanes)
            float pl[OUTD];
#pragma unroll
            for (int o = 0; o < OUTD; o++) pl[o] = h2 * wout[o];
#pragma unroll
            for (int d = 8; d >= 1; d >>= 1) {
#pragma unroll
                for (int o = 0; o < OUTD; o++)
                    pl[o] += __shfl_xor_sync(0x0000ffffu, pl[o], d, 16);
            }
            if (kl < OUTD) {
                float myv = pl[0];
#pragma unroll
                for (int o = 1; o < OUTD; o++) if (kl == o) myv = pl[o];
                const uint32_t poff = sm2u(&plog_s[p ^ 1][rank][b * OUTD + kl]);
#pragma unroll
                for (uint32_t rr = 0; rr < NCTA; rr++) dst_f32(poff, rr, myv);
            }
        }

        // ---- cluster sync; log-softmax(t-1) + STG hidden inside the window ----
        asm volatile("barrier.cluster.arrive.aligned;" ::: "memory");
        if (t > 0 && rank == 0 && evenw) {
            const int o = lane & 7;
            float e = (lane < 8 && o < OUTD) ? __expf(slog - vmax) : 0.f;
#pragma unroll
            for (int d = 4; d >= 1; d >>= 1)
                e += __shfl_xor_sync(FULLM, e, d, 8);
            const float lse = vmax + __logf(e);
            if (lane < OUTD)
                out[(size_t)b * TLEN * OUTD + (size_t)(t - 1) * OUTD + lane] = slog - lse;
        }
        asm volatile("barrier.cluster.wait.aligned;" ::: "memory");
    }

    // ================= epilogue: logits for t = TLEN-1, final states =================
    {
        const int o = lane & 7;
        float s = -1e30f;
        if (lane < 8 && o < OUTD) {
            s = bout_s[o];
#pragma unroll
            for (int rr = 0; rr < NCTA; rr++) s += plog_s[0][rr][b * OUTD + o];
        }
        float v = s;
#pragma unroll
        for (int d = 4; d >= 1; d >>= 1) {
            float v2 = __shfl_xor_sync(FULLM, v, d, 8);
            if (v2 > v) v = v2;
        }
        float e = (lane < 8 && o < OUTD) ? __expf(s - v) : 0.f;
#pragma unroll
        for (int d = 4; d >= 1; d >>= 1)
            e += __shfl_xor_sync(FULLM, e, d, 8);
        const float lse = v + __logf(e);
        if (rank == 0 && evenw && lane < OUTD)
            out[(size_t)b * TLEN * OUTD + (size_t)(TLEN - 1) * OUTD + lane] = s - lse;

        if (rank == 0) {
            for (int i = tid; i < BATCHN * HID; i += TPB)
                out[(size_t)BATCHN * TLEN * OUTD + i] = ((float*)h_s[0])[i];
        }
        if (is_pw)
            out[(size_t)BATCHN * TLEN * OUTD + BATCHN * HID + b * HID + kg] = cval;
    }
}

extern "C" void kernel_launch(void* const* d_in, const int* in_sizes, int n_in,
                              void* d_out, int out_size) {
    (void)in_sizes; (void)n_in; (void)out_size;
    const float* h0    = (const float*)d_in[0];
    const float* c0    = (const float*)d_in[1];
    const float* toh   = (const float*)d_in[2];
    const void*  tf    = d_in[3];
    const float* W_ih  = (const float*)d_in[4];
    const float* W_hh  = (const float*)d_in[5];
    const float* b_ih  = (const float*)d_in[6];
    const float* b_hh  = (const float*)d_in[7];
    const float* W_out = (const float*)d_in[8];
    const float* b_out = (const float*)d_in[9];
    float* out = (float*)d_out;

    lstm_decoder_kernel<<<NCTA, TPB>>>(h0, c0, toh, tf, W_ih, W_hh,
                                       b_ih, b_hh, W_out, b_out, out);
}

// round 5
// speedup vs baseline: 1.5975x; 1.5975x over previous
#include <cuda_runtime.h>
#include <cstdint>
#include <cstddef>

#define BATCHN 10
#define HID    128
#define OUTD   7
#define TLEN   2048
#define TPB    512     // thread = one gate row (4*HID = 512 rows); 16 warps

typedef unsigned long long ull;

__device__ __forceinline__ ull fma2(ull a, ull b, ull c) {
    ull d; asm("fma.rn.f32x2 %0, %1, %2, %3;" : "=l"(d) : "l"(a), "l"(b), "l"(c)); return d;
}
__device__ __forceinline__ ull pk2(float lo, float hi) {
    ull r; asm("mov.b64 %0, {%1, %2};" : "=l"(r) : "f"(lo), "f"(hi)); return r;
}
__device__ __forceinline__ float2 unpk2(ull v) {
    float2 f; asm("mov.b64 {%0, %1}, %2;" : "=f"(f.x), "=f"(f.y) : "l"(v)); return f;
}
__device__ __forceinline__ float fsig(float x)  { return __fdividef(1.f, 1.f + __expf(-x)); }
__device__ __forceinline__ float ftanh(float x) { return 2.f * __fdividef(1.f, 1.f + __expf(-2.f * x)) - 1.f; }

#define FULLM 0xffffffffu

// One CTA per batch. Entirely CTA-local recurrence: no cluster, no DSMEM.
__global__ void __launch_bounds__(TPB, 1)
lstm_decoder_kernel(const float* __restrict__ h0,
                    const float* __restrict__ c0,
                    const float* __restrict__ tonehot,   // (TLEN+1, 1, OUTD)
                    const void*  __restrict__ tfraw,     // tf_mask (dtype autodetect)
                    const float* __restrict__ W_ih,      // (4*HID, OUTD)
                    const float* __restrict__ W_hh,      // (4*HID, HID)
                    const float* __restrict__ b_ih,
                    const float* __restrict__ b_hh,
                    const float* __restrict__ W_out,     // (OUTD, HID)
                    const float* __restrict__ b_out,
                    float* __restrict__ out)             // [143360 lp | 1280 hT | 1280 cT]
{
    __shared__ __align__(16) float h_s[HID];       // single-buffered (barriers separate RW)
    __shared__ float gates_s[4 * HID];             // activated gates, row-indexed
    __shared__ float plog_s[4][OUTD];              // per-pw-warp logit partials
    __shared__ float wih_s[4 * HID * OUTD];
    __shared__ int   tgt_s[TLEN];
    __shared__ unsigned char tf_s[TLEN];
    __shared__ float bout_s[OUTD];
    __shared__ int   tfmode_s;

    const int b    = blockIdx.x;         // batch
    const int tid  = threadIdx.x;        // == gate row g (0..511)
    const int lane = tid & 31;
    const int wid  = tid >> 5;
    const int type = tid >> 7;           // 0=i 1=f 2=g 3=o

    // W_hh row (128 floats) packed into 64 u64 registers
    ull wp[HID / 2];
#pragma unroll
    for (int i = 0; i < HID / 4; i++) {
        float4 v = reinterpret_cast<const float4*>(W_hh + (size_t)tid * HID)[i];
        wp[2*i]   = pk2(v.x, v.y);
        wp[2*i+1] = pk2(v.z, v.w);
    }
    const float biasg = b_ih[tid] + b_hh[tid];
    const int   gbase = tid * OUTD;

    // pointwise role: tid < 128 owns hidden unit k = tid (warps 0..3)
    const bool is_pw = tid < HID;
    float cval = 0.f;
    float wout[OUTD];
    if (is_pw) {
        cval = c0[b * HID + tid];
#pragma unroll
        for (int o = 0; o < OUTD; o++) wout[o] = W_out[o * HID + tid];
    }

    // ---- init ----
    if (is_pw) h_s[tid] = h0[b * HID + tid];
    for (int i = tid; i < 4 * HID * OUTD; i += TPB) wih_s[i] = W_ih[i];
    if (tid < OUTD) bout_s[tid] = b_out[tid];
    if (tid == 0) {                                   // tf dtype autodetect
        const int* ip = (const int*)tfraw;
        int mode = 0;
        for (int i = 0; i < 512; i++) {
            int v = ip[i];
            if (v == 0x3f800000) { mode = 1; break; }
            if (v != 0 && v != 1) mode = 2;
        }
        tfmode_s = mode;
    }
    __syncthreads();
    {
        const int mode = tfmode_s;
        for (int s = tid; s < TLEN; s += TPB) {
            unsigned char tv;
            if (mode == 0)      tv = ((const int*)tfraw)[s] != 0;
            else if (mode == 1) tv = ((const float*)tfraw)[s] != 0.f;
            else                tv = ((const unsigned char*)tfraw)[s] != 0;
            tf_s[s] = tv;
            const float* row = tonehot + (size_t)(s + 1) * OUTD;   // exactly one-hot
            int idx = 0; float best = row[0];
#pragma unroll
            for (int o = 1; o < OUTD; o++) { if (row[o] > best) { best = row[o]; idx = o; } }
            tgt_s[s] = idx;
        }
    }
    __syncthreads();

    // ================= main sequential loop =================
    for (int t = 0; t < TLEN; t++) {
        // ---- recurrent dot: 64 f32x2 FMAs, 4 accumulators ----
        ull acc0 = 0ull, acc1 = 0ull, acc2 = 0ull, acc3 = 0ull;
        const ulonglong2* hb = reinterpret_cast<const ulonglong2*>(h_s);
#pragma unroll
        for (int i = 0; i < HID / 8; i++) {          // 16 iters, 2x ulonglong2 each
            ulonglong2 u0 = hb[2*i];
            ulonglong2 u1 = hb[2*i + 1];
            acc0 = fma2(u0.x, wp[4*i],     acc0);
            acc1 = fma2(u0.y, wp[4*i + 1], acc1);
            acc2 = fma2(u1.x, wp[4*i + 2], acc2);
            acc3 = fma2(u1.y, wp[4*i + 3], acc3);
        }

        // ---- argmax of logits(t-1), redundant per warp (overlaps other warps' FMA issue) ----
        int xb = OUTD - 1;
        float slog = -1e30f, vmax = -1e30f;
        if (t > 0) {
            const int o = lane & 7;
            float s = -1e30f;
            if (lane < 8 && o < OUTD) {
                s = bout_s[o] + plog_s[0][o] + plog_s[1][o] + plog_s[2][o] + plog_s[3][o];
            }
            float v = s;
            int   idx = (lane < 8 && o < OUTD) ? o : OUTD;
#pragma unroll
            for (int d = 4; d >= 1; d >>= 1) {
                float v2 = __shfl_xor_sync(FULLM, v, d, 8);
                int   i2 = __shfl_xor_sync(FULLM, idx, d, 8);
                if (v2 > v || (v2 == v && i2 < idx)) { v = v2; idx = i2; }
            }
            slog = s; vmax = v;
            const int ia = __shfl_sync(FULLM, idx, 0);
            xb = tf_s[t - 1] ? tgt_s[t - 1] : ia;
        }

        // ---- finish gate: bias + one-hot input column, activate ----
        float2 f0 = unpk2(acc0), f1 = unpk2(acc1), f2 = unpk2(acc2), f3 = unpk2(acc3);
        float vb = ((f0.x + f0.y) + (f1.x + f1.y)) + ((f2.x + f2.y) + (f3.x + f3.y))
                 + biasg + wih_s[gbase + xb];
        vb = (type == 2) ? ftanh(vb) : fsig(vb);
        gates_s[tid] = vb;

        __syncthreads();   // bar1: gates ready; h_s reads (dot) complete

        if (is_pw) {
            // ---- pointwise for hidden unit k = tid ----
            const float ig = gates_s[tid];
            const float fg = gates_s[tid + HID];
            const float gg = gates_s[tid + 2 * HID];
            const float og = gates_s[tid + 3 * HID];
            cval = fg * cval + ig * gg;
            const float h2 = og * ftanh(cval);
            h_s[tid] = h2;

            // logit partials: reduce h2*wout over the 32 lanes of this pw warp
            float pl[OUTD];
#pragma unroll
            for (int o = 0; o < OUTD; o++) pl[o] = h2 * wout[o];
#pragma unroll
            for (int d = 16; d >= 1; d >>= 1) {
#pragma unroll
                for (int o = 0; o < OUTD; o++)
                    pl[o] += __shfl_xor_sync(FULLM, pl[o], d);
            }
            if (lane < OUTD) {
                float myv = pl[0];
#pragma unroll
                for (int o = 1; o < OUTD; o++) if (lane == o) myv = pl[o];
                plog_s[wid][lane] = myv;
            }
        } else if (wid == 4 && t > 0) {
            // ---- log-softmax(t-1) + store, off the critical path ----
            const int o = lane & 7;
            float e = (lane < 8 && o < OUTD) ? __expf(slog - vmax) : 0.f;
#pragma unroll
            for (int d = 4; d >= 1; d >>= 1)
                e += __shfl_xor_sync(FULLM, e, d, 8);
            const float lse = vmax + __logf(e);
            if (lane < OUTD)
                out[(size_t)b * TLEN * OUTD + (size_t)(t - 1) * OUTD + lane] = slog - lse;
        }

        __syncthreads();   // bar2: h_s(t+1) + plog ready for next step
    }

    // ================= epilogue: logits for t = TLEN-1, final states =================
    {
        const int o = lane & 7;
        float s = -1e30f;
        if (lane < 8 && o < OUTD)
            s = bout_s[o] + plog_s[0][o] + plog_s[1][o] + plog_s[2][o] + plog_s[3][o];
        float v = s;
#pragma unroll
        for (int d = 4; d >= 1; d >>= 1) {
            float v2 = __shfl_xor_sync(FULLM, v, d, 8);
            if (v2 > v) v = v2;
        }
        float e = (lane < 8 && o < OUTD) ? __expf(s - v) : 0.f;
#pragma unroll
        for (int d = 4; d >= 1; d >>= 1)
            e += __shfl_xor_sync(FULLM, e, d, 8);
        const float lse = v + __logf(e);
        if (wid == 4 && lane < OUTD)
            out[(size_t)b * TLEN * OUTD + (size_t)(TLEN - 1) * OUTD + lane] = s - lse;

        if (is_pw) {
            out[(size_t)BATCHN * TLEN * OUTD + b * HID + tid] = h_s[tid];
            out[(size_t)BATCHN * TLEN * OUTD + BATCHN * HID + b * HID + tid] = cval;
        }
    }
}

extern "C" void kernel_launch(void* const* d_in, const int* in_sizes, int n_in,
                              void* d_out, int out_size) {
    (void)in_sizes; (void)n_in; (void)out_size;
    const float* h0    = (const float*)d_in[0];
    const float* c0    = (const float*)d_in[1];
    const float* toh   = (const float*)d_in[2];
    const void*  tf    = d_in[3];
    const float* W_ih  = (const float*)d_in[4];
    const float* W_hh  = (const float*)d_in[5];
    const float* b_ih  = (const float*)d_in[6];
    const float* b_hh  = (const float*)d_in[7];
    const float* W_out = (const float*)d_in[8];
    const float* b_out = (const float*)d_in[9];
    float* out = (float*)d_out;

    lstm_decoder_kernel<<<BATCHN, TPB>>>(h0, c0, toh, tf, W_ih, W_hh,
                                         b_ih, b_hh, W_out, b_out, out);
}

// round 6
// speedup vs baseline: 2.6635x; 1.6673x over previous
#include <cuda_runtime.h>
#include <cstdint>
#include <cstddef>

#define BATCHN 10
#define HID    128
#define OUTD   7
#define TLEN   2048
#define TPB    512       // thread = one gate row; 16 warps
#define WSMC   68        // smem weight tile row stride (64 cols + 4 pad, conflict-free)

typedef unsigned long long ull;

__device__ __forceinline__ ull fma2(ull a, ull b, ull c) {
    ull d; asm("fma.rn.f32x2 %0, %1, %2, %3;" : "=l"(d) : "l"(a), "l"(b), "l"(c)); return d;
}
__device__ __forceinline__ ull pk2(float lo, float hi) {
    ull r; asm("mov.b64 %0, {%1, %2};" : "=l"(r) : "f"(lo), "f"(hi)); return r;
}
__device__ __forceinline__ float2 unpk2(ull v) {
    float2 f; asm("mov.b64 {%0, %1}, %2;" : "=f"(f.x), "=f"(f.y) : "l"(v)); return f;
}
__device__ __forceinline__ float fsig(float x)  { return __fdividef(1.f, 1.f + __expf(-x)); }
__device__ __forceinline__ float ftanh(float x) { return 2.f * __fdividef(1.f, 1.f + __expf(-2.f * x)) - 1.f; }

#define FULLM 0xffffffffu

// One CTA per batch, CTA-local recurrence. W_hh row split: cols 0..63 in
// registers (32 packed u64), cols 64..127 in a padded smem tile (no spills).
__global__ void __launch_bounds__(TPB, 1)
lstm_decoder_kernel(const float* __restrict__ h0,
                    const float* __restrict__ c0,
                    const float* __restrict__ tonehot,   // (TLEN+1, 1, OUTD)
                    const void*  __restrict__ tfraw,     // tf_mask (dtype autodetect)
                    const float* __restrict__ W_ih,      // (4*HID, OUTD)
                    const float* __restrict__ W_hh,      // (4*HID, HID)
                    const float* __restrict__ b_ih,
                    const float* __restrict__ b_hh,
                    const float* __restrict__ W_out,     // (OUTD, HID)
                    const float* __restrict__ b_out,
                    float* __restrict__ out)             // [143360 lp | 1280 hT | 1280 cT]
{
    extern __shared__ __align__(16) float dyn_s[];
    float* wsm   = dyn_s;                        // [4*HID][WSMC]  cols 64..127 of W_hh
    float* wih_s = dyn_s + 4 * HID * WSMC;       // [4*HID*OUTD]

    __shared__ __align__(16) float h_s[HID];
    __shared__ float gates_s[4 * HID];
    __shared__ float plog_s[4][OUTD];
    __shared__ int   tgt_s[TLEN];
    __shared__ unsigned char tf_s[TLEN];
    __shared__ float bout_s[OUTD];
    __shared__ int   tfmode_s;

    const int b    = blockIdx.x;
    const int tid  = threadIdx.x;        // == gate row (0..511)
    const int lane = tid & 31;
    const int wid  = tid >> 5;
    const int type = tid >> 7;           // 0=i 1=f 2=g 3=o

    // cols 0..63 of W_hh row -> 32 packed u64 (64 regs)
    ull wp[32];
#pragma unroll
    for (int i = 0; i < 16; i++) {
        float4 v = reinterpret_cast<const float4*>(W_hh + (size_t)tid * HID)[i];
        wp[2*i]   = pk2(v.x, v.y);
        wp[2*i+1] = pk2(v.z, v.w);
    }
    // cols 64..127 -> smem tile
    {
        const float4* src = reinterpret_cast<const float4*>(W_hh + (size_t)tid * HID + 64);
        float* dst = wsm + tid * WSMC;
#pragma unroll
        for (int i = 0; i < 16; i++) {
            float4 v = src[i];
            dst[4*i] = v.x; dst[4*i+1] = v.y; dst[4*i+2] = v.z; dst[4*i+3] = v.w;
        }
    }
    const float biasg = b_ih[tid] + b_hh[tid];
    const int   gbase = tid * OUTD;

    // pointwise role: tid < 128 owns hidden unit k = tid (warps 0..3)
    const bool is_pw = tid < HID;
    float cval = 0.f;
    float wout[OUTD];
    if (is_pw) {
        cval = c0[b * HID + tid];
#pragma unroll
        for (int o = 0; o < OUTD; o++) wout[o] = W_out[o * HID + tid];
    }

    // ---- init ----
    if (is_pw) h_s[tid] = h0[b * HID + tid];
    for (int i = tid; i < 4 * HID * OUTD; i += TPB) wih_s[i] = W_ih[i];
    if (tid < OUTD) bout_s[tid] = b_out[tid];
    if (tid == 0) {                                   // tf dtype autodetect
        const int* ip = (const int*)tfraw;
        int mode = 0;
        for (int i = 0; i < 512; i++) {
            int v = ip[i];
            if (v == 0x3f800000) { mode = 1; break; }
            if (v != 0 && v != 1) mode = 2;
        }
        tfmode_s = mode;
    }
    __syncthreads();
    {
        const int mode = tfmode_s;
        for (int s = tid; s < TLEN; s += TPB) {
            unsigned char tv;
            if (mode == 0)      tv = ((const int*)tfraw)[s] != 0;
            else if (mode == 1) tv = ((const float*)tfraw)[s] != 0.f;
            else                tv = ((const unsigned char*)tfraw)[s] != 0;
            tf_s[s] = tv;
            const float* row = tonehot + (size_t)(s + 1) * OUTD;   // exactly one-hot
            int idx = 0; float best = row[0];
#pragma unroll
            for (int o = 1; o < OUTD; o++) { if (row[o] > best) { best = row[o]; idx = o; } }
            tgt_s[s] = idx;
        }
    }
    __syncthreads();

    const ulonglong2* wr = reinterpret_cast<const ulonglong2*>(wsm + tid * WSMC);

    // ================= main sequential loop =================
    for (int t = 0; t < TLEN; t++) {
        // ---- recurrent dot: reg half (cols 0..63) + smem half (cols 64..127) ----
        ull acc0 = 0ull, acc1 = 0ull, acc2 = 0ull, acc3 = 0ull;
        const ulonglong2* hb = reinterpret_cast<const ulonglong2*>(h_s);
#pragma unroll
        for (int i = 0; i < 16; i++) {
            ulonglong2 u = hb[i];            // h cols 4i..4i+3 (broadcast)
            acc0 = fma2(u.x, wp[2*i],   acc0);
            acc1 = fma2(u.y, wp[2*i+1], acc1);
            ulonglong2 v = hb[16 + i];       // h cols 64+4i.. (broadcast)
            ulonglong2 wv = wr[i];           // own-row weights (conflict-free)
            acc2 = fma2(v.x, wv.x, acc2);
            acc3 = fma2(v.y, wv.y, acc3);
        }

        // ---- argmax of logits(t-1), redundant per warp ----
        int xb = OUTD - 1;
        float slog = -1e30f, vmax = -1e30f;
        if (t > 0) {
            const int o = lane & 7;
            float s = -1e30f;
            if (lane < 8 && o < OUTD)
                s = bout_s[o] + plog_s[0][o] + plog_s[1][o] + plog_s[2][o] + plog_s[3][o];
            float v = s;
            int   idx = (lane < 8 && o < OUTD) ? o : OUTD;
#pragma unroll
            for (int d = 4; d >= 1; d >>= 1) {
                float v2 = __shfl_xor_sync(FULLM, v, d, 8);
                int   i2 = __shfl_xor_sync(FULLM, idx, d, 8);
                if (v2 > v || (v2 == v && i2 < idx)) { v = v2; idx = i2; }
            }
            slog = s; vmax = v;
            const int ia = __shfl_sync(FULLM, idx, 0);
            xb = tf_s[t - 1] ? tgt_s[t - 1] : ia;
        }

        // ---- finish gate: bias + one-hot input column, activate ----
        float2 f0 = unpk2(acc0), f1 = unpk2(acc1), f2 = unpk2(acc2), f3 = unpk2(acc3);
        float vb = ((f0.x + f0.y) + (f1.x + f1.y)) + ((f2.x + f2.y) + (f3.x + f3.y))
                 + biasg + wih_s[gbase + xb];
        vb = (type == 2) ? ftanh(vb) : fsig(vb);
        gates_s[tid] = vb;

        __syncthreads();   // gates ready; h_s dot-reads complete

        if (is_pw) {
            const float ig = gates_s[tid];
            const float fg = gates_s[tid + HID];
            const float gg = gates_s[tid + 2 * HID];
            const float og = gates_s[tid + 3 * HID];
            cval = fg * cval + ig * gg;
            const float h2 = og * ftanh(cval);
            h_s[tid] = h2;

            float pl[OUTD];
#pragma unroll
            for (int o = 0; o < OUTD; o++) pl[o] = h2 * wout[o];
#pragma unroll
            for (int d = 16; d >= 1; d >>= 1) {
#pragma unroll
                for (int o = 0; o < OUTD; o++)
                    pl[o] += __shfl_xor_sync(FULLM, pl[o], d);
            }
            if (lane < OUTD) {
                float myv = pl[0];
#pragma unroll
                for (int o = 1; o < OUTD; o++) if (lane == o) myv = pl[o];
                plog_s[wid][lane] = myv;
            }
        } else if (wid == 4 && t > 0) {
            // log-softmax(t-1) + store, off the critical path
            const int o = lane & 7;
            float e = (lane < 8 && o < OUTD) ? __expf(slog - vmax) : 0.f;
#pragma unroll
            for (int d = 4; d >= 1; d >>= 1)
                e += __shfl_xor_sync(FULLM, e, d, 8);
            const float lse = vmax + __logf(e);
            if (lane < OUTD)
                out[(size_t)b * TLEN * OUTD + (size_t)(t - 1) * OUTD + lane] = slog - lse;
        }

        __syncthreads();   // h_s(t+1) + plog ready
    }

    // ================= epilogue =================
    {
        const int o = lane & 7;
        float s = -1e30f;
        if (lane < 8 && o < OUTD)
            s = bout_s[o] + plog_s[0][o] + plog_s[1][o] + plog_s[2][o] + plog_s[3][o];
        float v = s;
#pragma unroll
        for (int d = 4; d >= 1; d >>= 1) {
            float v2 = __shfl_xor_sync(FULLM, v, d, 8);
            if (v2 > v) v = v2;
        }
        float e = (lane < 8 && o < OUTD) ? __expf(s - v) : 0.f;
#pragma unroll
        for (int d = 4; d >= 1; d >>= 1)
            e += __shfl_xor_sync(FULLM, e, d, 8);
        const float lse = v + __logf(e);
        if (wid == 4 && lane < OUTD)
            out[(size_t)b * TLEN * OUTD + (size_t)(TLEN - 1) * OUTD + lane] = s - lse;

        if (is_pw) {
            out[(size_t)BATCHN * TLEN * OUTD + b * HID + tid] = h_s[tid];
            out[(size_t)BATCHN * TLEN * OUTD + BATCHN * HID + b * HID + tid] = cval;
        }
    }
}

extern "C" void kernel_launch(void* const* d_in, const int* in_sizes, int n_in,
                              void* d_out, int out_size) {
    (void)in_sizes; (void)n_in; (void)out_size;
    const float* h0    = (const float*)d_in[0];
    const float* c0    = (const float*)d_in[1];
    const float* toh   = (const float*)d_in[2];
    const void*  tf    = d_in[3];
    const float* W_ih  = (const float*)d_in[4];
    const float* W_hh  = (const float*)d_in[5];
    const float* b_ih  = (const float*)d_in[6];
    const float* b_hh  = (const float*)d_in[7];
    const float* W_out = (const float*)d_in[8];
    const float* b_out = (const float*)d_in[9];
    float* out = (float*)d_out;

    const size_t dyn_bytes = (size_t)(4 * HID * WSMC + 4 * HID * OUTD) * sizeof(float);
    cudaFuncSetAttribute(lstm_decoder_kernel,
                         cudaFuncAttributeMaxDynamicSharedMemorySize, (int)dyn_bytes);
    lstm_decoder_kernel<<<BATCHN, TPB, dyn_bytes>>>(h0, c0, toh, tf, W_ih, W_hh,
                                                    b_ih, b_hh, W_out, b_out, out);
}